// round 2
// baseline (speedup 1.0000x reference)
#include <cuda_runtime.h>
#include <stdint.h>

// Problem constants
#define B_   2
#define N_   2048
#define D_   1024
#define H_   16
#define HD_  64
#define BH_  (B_*H_)   // 32
#define R_   (B_*N_)   // 4096

// ---------------- device scratch (no allocations allowed) ----------------
__device__ int8_t g_xq[R_*D_];          // quantized hidden states [r][d]
__device__ int8_t g_wq[4][D_*D_];       // quantized weights q,k,v,o  [out][in]
__device__ int    g_b32[4][D_];         // bias*32 as int
__device__ int8_t g_q8[BH_*N_*HD_];     // quantize(q*scaling)  [bh][n][hd]
__device__ int8_t g_k8[BH_*N_*HD_];     // quantize(k)          [bh][n][hd]
__device__ int8_t g_v8t[BH_*HD_*N_];    // quantize(v) transposed [bh][hd][n]
__device__ int8_t g_cq[R_*D_];          // quantized ctx        [r][d]

// ---------------- helpers ----------------
__device__ __forceinline__ int8_t quant8(float x) {
    float v = rintf(x * 32.f);               // round-half-even, matches jnp.round
    v = fminf(fmaxf(v, -128.f), 127.f);
    return (int8_t)(int)v;
}

// FFMA-only exp (avoids MUFU.EX2 throughput ceiling).  x <= 0 always here.
__device__ __forceinline__ float fast_exp_neg(float x) {
    float y = fmaxf(x * 1.4426950408889634f, -126.f);
    float n = rintf(y);
    float f = y - n;                          // f in [-0.5, 0.5]
    float p =              1.5252733804059841e-5f;
    p = fmaf(p, f,         1.5403530393381606e-4f);
    p = fmaf(p, f,         1.3333558146428443e-3f);
    p = fmaf(p, f,         9.6181291076284772e-3f);
    p = fmaf(p, f,         5.5504108664821580e-2f);
    p = fmaf(p, f,         2.4022650695910071e-1f);
    p = fmaf(p, f,         6.9314718055994531e-1f);
    p = fmaf(p, f,         1.0f);
    float s = __int_as_float(((int)n + 127) << 23);   // 2^n, n in [-126,0]
    return p * s;
}

// ---------------- quantize kernels ----------------
__global__ void k_quant_x(const float* __restrict__ x) {
    int i = blockIdx.x * blockDim.x + threadIdx.x;
    if (i < R_*D_) g_xq[i] = quant8(x[i]);
}
__global__ void k_quant_w(const float* __restrict__ w, int idx) {
    int i = blockIdx.x * blockDim.x + threadIdx.x;
    if (i < D_*D_) g_wq[idx][i] = quant8(w[i]);
}
__global__ void k_quant_b(const float* __restrict__ qb, const float* __restrict__ kb,
                          const float* __restrict__ vb, const float* __restrict__ ob) {
    int i = blockIdx.x * blockDim.x + threadIdx.x;
    if (i < D_) {
        float v;
        v = rintf(qb[i]*32.f); g_b32[0][i] = (int)fminf(fmaxf(v,-128.f),127.f);
        v = rintf(kb[i]*32.f); g_b32[1][i] = (int)fminf(fmaxf(v,-128.f),127.f);
        v = rintf(vb[i]*32.f); g_b32[2][i] = (int)fminf(fmaxf(v,-128.f),127.f);
        v = rintf(ob[i]*32.f); g_b32[3][i] = (int)fminf(fmaxf(v,-128.f),127.f);
    }
}

// ---------------- int8 GEMM (dp4a), 64x64 tile, 4x4 microtile ----------------
// C[r][o] = sum_k A[r][k] * W[o][k]   (K = 1024)
// MODE 0: Q epilogue  -> g_q8   (quantize((acc/1024 + b)/8))
// MODE 1: K epilogue  -> g_k8   (quantize(acc/1024 + b))
// MODE 2: V epilogue  -> g_v8t  (same value, transposed layout)
// MODE 3: O epilogue  -> float out = acc/1024 + b
template<int MODE>
__global__ void __launch_bounds__(256) k_gemm(float* __restrict__ outf) {
    __shared__ int sAt[16][64];   // K-major: sAt[kint][row-in-tile]
    __shared__ int sBt[16][64];
    const int* A = (const int*)((MODE == 3) ? g_cq : g_xq);
    const int* W = (const int*)g_wq[MODE];
    const int t  = threadIdx.x;
    const int tx = t & 15, ty = t >> 4;       // 16x16 thread grid
    const int r0 = blockIdx.y << 6, o0 = blockIdx.x << 6;
    const int lr = t >> 2, li = t & 3;        // tile loaders: 64 rows x 4 int4

    int acc[4][4];
#pragma unroll
    for (int i = 0; i < 4; i++)
#pragma unroll
        for (int j = 0; j < 4; j++) acc[i][j] = 0;

    const int4* Ag = (const int4*)(A + (r0 + lr) * (D_/4));
    const int4* Wg = (const int4*)(W + (o0 + lr) * (D_/4));

    for (int kc = 0; kc < D_/64; kc++) {
        int4 av = Ag[kc*4 + li];
        int4 bv = Wg[kc*4 + li];
        __syncthreads();
        sAt[li*4+0][lr] = av.x; sAt[li*4+1][lr] = av.y;
        sAt[li*4+2][lr] = av.z; sAt[li*4+3][lr] = av.w;
        sBt[li*4+0][lr] = bv.x; sBt[li*4+1][lr] = bv.y;
        sBt[li*4+2][lr] = bv.z; sBt[li*4+3][lr] = bv.w;
        __syncthreads();
#pragma unroll
        for (int k = 0; k < 16; k++) {
            int4 a4 = *(const int4*)&sAt[k][ty*4];
            int4 b4 = *(const int4*)&sBt[k][tx*4];
            int aa[4] = {a4.x, a4.y, a4.z, a4.w};
            int bb[4] = {b4.x, b4.y, b4.z, b4.w};
#pragma unroll
            for (int i = 0; i < 4; i++)
#pragma unroll
                for (int j = 0; j < 4; j++)
                    acc[i][j] = __dp4a(aa[i], bb[j], acc[i][j]);
        }
    }

#pragma unroll
    for (int i = 0; i < 4; i++) {
        int r = r0 + ty*4 + i;
#pragma unroll
        for (int j = 0; j < 4; j++) {
            int o = o0 + tx*4 + j;
            int a = acc[i][j];
            if (MODE == 3) {
                outf[r*D_ + o] = (float)a * (1.f/1024.f) + (float)g_b32[3][o] * (1.f/32.f);
            } else {
                int b32 = g_b32[MODE][o];
                float v;
                if (MODE == 0) v = rintf((float)(a + 32*b32) * (1.f/256.f));
                else           v = rintf((float)(a + 32*b32) * (1.f/32.f));
                v = fminf(fmaxf(v, -128.f), 127.f);
                int8_t q = (int8_t)(int)v;
                int b = r >> 11, n = r & (N_-1);
                int h = o >> 6,  hd = o & (HD_-1);
                int bh = b*H_ + h;
                if      (MODE == 0) g_q8 [(size_t)(bh*N_ + n)*HD_ + hd] = q;
                else if (MODE == 1) g_k8 [(size_t)(bh*N_ + n)*HD_ + hd] = q;
                else                g_v8t[(size_t)(bh*HD_ + hd)*N_ + n] = q;
            }
        }
    }
}

// ---------------- fused attention: S -> softmax -> quantize(P) -> P@V ----------------
// One block = (bh, 16 query rows). S tile 16x2048 int32 lives in smem.
__global__ void __launch_bounds__(256) k_attn(const float* __restrict__ mask) {
    extern __shared__ int smem[];
    int*   S     = smem;                       // 16*2048 ints (later floats)
    int*   skt   = smem + 16*2048;             // 16*256 (K-major k tile)
    int*   P4    = skt  + 16*256;              // 16*512 (packed int8 probs)
    float* red   = (float*)(P4 + 16*512);      // 256
    float* rowmx = red + 256;                  // 16
    float* rowz  = rowmx + 16;                 // 16

    const int bh = blockIdx.y, rb = blockIdx.x;
    const int t  = threadIdx.x;

    // ---- Phase A: S = q8 . k8^T (exact int32) ----
    const int rg = t >> 5, cg = t & 31;        // 8 rowgroups x 32 colgroups; micro 2x8
    const int* qrow = (const int*)g_q8 + (size_t)(bh*N_ + rb*16) * (HD_/4);
    int areg[2][16];
#pragma unroll
    for (int i = 0; i < 2; i++) {
        const int* p = qrow + (rg*2 + i) * 16;
#pragma unroll
        for (int k = 0; k < 16; k++) areg[i][k] = p[k];
    }

    for (int pass = 0; pass < 8; pass++) {
        int col0 = pass * 256;
        const int4* ks = (const int4*)(g_k8 + (size_t)(bh*N_ + col0 + t) * HD_);
        int4 kv0 = ks[0], kv1 = ks[1], kv2 = ks[2], kv3 = ks[3];
        int kvals[16] = {kv0.x,kv0.y,kv0.z,kv0.w, kv1.x,kv1.y,kv1.z,kv1.w,
                         kv2.x,kv2.y,kv2.z,kv2.w, kv3.x,kv3.y,kv3.z,kv3.w};
        __syncthreads();
#pragma unroll
        for (int w = 0; w < 16; w++) skt[w*256 + t] = kvals[w];
        __syncthreads();

        int acc[2][8];
#pragma unroll
        for (int i = 0; i < 2; i++)
#pragma unroll
            for (int j = 0; j < 8; j++) acc[i][j] = 0;

#pragma unroll
        for (int k = 0; k < 16; k++) {
            const int4* bp = (const int4*)(skt + k*256 + cg*8);
            int4 b0 = bp[0], b1 = bp[1];
            int bb[8] = {b0.x,b0.y,b0.z,b0.w, b1.x,b1.y,b1.z,b1.w};
            int a0 = areg[0][k], a1 = areg[1][k];
#pragma unroll
            for (int j = 0; j < 8; j++) {
                acc[0][j] = __dp4a(a0, bb[j], acc[0][j]);
                acc[1][j] = __dp4a(a1, bb[j], acc[1][j]);
            }
        }
#pragma unroll
        for (int i = 0; i < 2; i++)
#pragma unroll
            for (int j = 0; j < 8; j++)
                S[(rg*2 + i)*2048 + col0 + cg*8 + j] = acc[i][j];
    }
    __syncthreads();

    // ---- Phase B: softmax + quantize probabilities ----
    float* Sf = (float*)S;
    const int row = t >> 4, part = t & 15;
    const int bb_ = bh / H_;
    const float* mrow = mask + ((size_t)bb_*N_ + rb*16 + row) * N_;

    float mx = -3.402823466e38f;
    for (int c = part; c < 2048; c += 16) {
        float sc = (float)S[row*2048 + c] * (1.f/1024.f) + mrow[c];
        sc = fmaxf(sc, -3.402823466e38f);     // jnp.maximum(attn, finfo.min)
        Sf[row*2048 + c] = sc;
        mx = fmaxf(mx, sc);
    }
    red[t] = mx;
    __syncthreads();
    if (part == 0) {
        float m = red[row*16];
#pragma unroll
        for (int k = 1; k < 16; k++) m = fmaxf(m, red[row*16 + k]);
        rowmx[row] = m;
    }
    __syncthreads();

    float m = rowmx[row];
    float z = 0.f;
    for (int c = part; c < 2048; c += 16) {
        float e = fast_exp_neg(Sf[row*2048 + c] - m);
        Sf[row*2048 + c] = e;
        z += e;
    }
    red[t] = z;
    __syncthreads();
    if (part == 0) {
        float s = 0.f;
#pragma unroll
        for (int k = 0; k < 16; k++) s += red[row*16 + k];
        rowz[row] = s;
    }
    __syncthreads();

    float Z = rowz[row];
    for (int j = part; j < 512; j += 16) {
        float e0 = Sf[row*2048 + 4*j + 0];
        float e1 = Sf[row*2048 + 4*j + 1];
        float e2 = Sf[row*2048 + 4*j + 2];
        float e3 = Sf[row*2048 + 4*j + 3];
        int p0 = (int)fminf(rintf(32.f * (e0 / Z)), 127.f);
        int p1 = (int)fminf(rintf(32.f * (e1 / Z)), 127.f);
        int p2 = (int)fminf(rintf(32.f * (e2 / Z)), 127.f);
        int p3 = (int)fminf(rintf(32.f * (e3 / Z)), 127.f);
        P4[row*512 + j] = (p0 & 255) | ((p1 & 255) << 8) | ((p2 & 255) << 16) | ((p3 & 255) << 24);
    }
    __syncthreads();

    // ---- Phase C: ctx = P . V (dp4a over packed probs / transposed V) ----
    {
        const int r  = t >> 4, hl = t & 15;
        const int4* Pp = (const int4*)(P4 + r*512);
        const int n  = rb*16 + r;
        const int h  = bh % H_;
        int8_t* cdst = g_cq + (size_t)(bb_ /*== bh/H_*/ * N_ + n) * D_ + h*HD_;
#pragma unroll
        for (int it = 0; it < 4; it++) {
            int hd = hl + 16*it;
            const int4* Vp = (const int4*)(g_v8t + (size_t)(bh*HD_ + hd) * N_);
            int acc = 0;
#pragma unroll 4
            for (int j4 = 0; j4 < 128; j4++) {
                int4 pv = Pp[j4];
                int4 vv = Vp[j4];
                acc = __dp4a(pv.x, vv.x, acc);
                acc = __dp4a(pv.y, vv.y, acc);
                acc = __dp4a(pv.z, vv.z, acc);
                acc = __dp4a(pv.w, vv.w, acc);
            }
            float v = rintf((float)acc * (1.f/32.f));   // quantize(acc/1024)*32
            v = fminf(fmaxf(v, -128.f), 127.f);
            cdst[hd] = (int8_t)(int)v;
        }
    }
}

// ---------------- launcher ----------------
extern "C" void kernel_launch(void* const* d_in, const int* in_sizes, int n_in,
                              void* d_out, int out_size) {
    const float* hidden = (const float*)d_in[0];
    const float* amask  = (const float*)d_in[1];
    const float* q_w = (const float*)d_in[2]; const float* q_b = (const float*)d_in[3];
    const float* k_w = (const float*)d_in[4]; const float* k_b = (const float*)d_in[5];
    const float* v_w = (const float*)d_in[6]; const float* v_b = (const float*)d_in[7];
    const float* o_w = (const float*)d_in[8]; const float* o_b = (const float*)d_in[9];
    float* out = (float*)d_out;

    static bool attr_set = false;
    if (!attr_set) {
        cudaFuncSetAttribute(k_attn, cudaFuncAttributeMaxDynamicSharedMemorySize, 181376);
        attr_set = true;
    }

    // 1) quantize inputs
    k_quant_x<<<(R_*D_ + 255)/256, 256>>>(hidden);
    k_quant_w<<<(D_*D_ + 255)/256, 256>>>(q_w, 0);
    k_quant_w<<<(D_*D_ + 255)/256, 256>>>(k_w, 1);
    k_quant_w<<<(D_*D_ + 255)/256, 256>>>(v_w, 2);
    k_quant_w<<<(D_*D_ + 255)/256, 256>>>(o_w, 3);
    k_quant_b<<<(D_ + 255)/256, 256>>>(q_b, k_b, v_b, o_b);

    // 2) projections (int8 GEMM + fused quantize epilogues)
    dim3 gdim(D_/64, R_/64);
    k_gemm<0><<<gdim, 256>>>(nullptr);
    k_gemm<1><<<gdim, 256>>>(nullptr);
    k_gemm<2><<<gdim, 256>>>(nullptr);

    // 3) fused attention
    k_attn<<<dim3(N_/16, BH_), 256, 181376>>>(amask);

    // 4) output projection -> fp32
    k_gemm<3><<<gdim, 256>>>(out);
}

// round 6
// speedup vs baseline: 3.7282x; 3.7282x over previous
#include <cuda_runtime.h>
#include <stdint.h>

// Problem constants
#define B_   2
#define N_   2048
#define D_   1024
#define H_   16
#define HD_  64
#define BH_  (B_*H_)   // 32
#define R_   (B_*N_)   // 4096

#define FMIN_ (-3.402823466e38f)

// ---------------- device scratch (no allocations allowed) ----------------
__device__ __align__(16) int8_t g_xq[R_*D_];
__device__ __align__(16) int8_t g_wq[4][D_*D_];
__device__ int    g_b32[4][D_];
__device__ __align__(16) int8_t g_q8[BH_*N_*HD_];
__device__ __align__(16) int8_t g_k8[BH_*N_*HD_];
__device__ __align__(16) int8_t g_v8t[BH_*HD_*N_];
__device__ __align__(16) int8_t g_cq[R_*D_];

// ---------------- base-ISA PTX helpers (no sm_103a features) ----------------
__device__ __forceinline__ uint32_t smem_u32(const void* p) {
    uint32_t a;
    asm("{ .reg .u64 t; cvta.to.shared.u64 t, %1; cvt.u32.u64 %0, t; }" : "=r"(a) : "l"(p));
    return a;
}
__device__ __forceinline__ void cpa16(uint32_t dst, const void* src) {
    uint64_t g = __cvta_generic_to_global(src);
    asm volatile("cp.async.cg.shared.global [%0], [%1], 16;" :: "r"(dst), "l"(g) : "memory");
}
#define CPC()  asm volatile("cp.async.commit_group;" ::: "memory")
#define CPW(n) asm volatile("cp.async.wait_group %0;" :: "n"(n) : "memory")

__device__ __forceinline__ void ldsm4(uint32_t a[4], uint32_t addr) {
    asm volatile("ldmatrix.sync.aligned.m8n8.x4.shared.b16 {%0,%1,%2,%3}, [%4];"
        : "=r"(a[0]), "=r"(a[1]), "=r"(a[2]), "=r"(a[3]) : "r"(addr));
}
__device__ __forceinline__ void mma16832(int c[4], const uint32_t a[4],
                                         uint32_t b0, uint32_t b1) {
    asm volatile(
        "mma.sync.aligned.m16n8k32.row.col.s32.s8.s8.s32 "
        "{%0,%1,%2,%3}, {%4,%5,%6,%7}, {%8,%9}, {%0,%1,%2,%3};"
        : "+r"(c[0]), "+r"(c[1]), "+r"(c[2]), "+r"(c[3])
        : "r"(a[0]), "r"(a[1]), "r"(a[2]), "r"(a[3]), "r"(b0), "r"(b1));
}

// ---------------- quantize kernels ----------------
__device__ __forceinline__ uint32_t qb(float x) {
    float v = rintf(x * 32.f);
    v = fminf(fmaxf(v, -128.f), 127.f);
    return (uint32_t)(int)v & 255u;
}
__device__ __forceinline__ uint32_t q4(float4 v) {
    return qb(v.x) | (qb(v.y) << 8) | (qb(v.z) << 16) | (qb(v.w) << 24);
}
__global__ void k_quant_x(const float4* __restrict__ x) {
    int i = blockIdx.x * blockDim.x + threadIdx.x;
    if (i < R_*D_/4) ((uint32_t*)g_xq)[i] = q4(x[i]);
}
__global__ void k_quant_w4(const float4* __restrict__ w0, const float4* __restrict__ w1,
                           const float4* __restrict__ w2, const float4* __restrict__ w3) {
    int i = blockIdx.x * blockDim.x + threadIdx.x;
    if (i < D_*D_/4) {
        ((uint32_t*)g_wq[0])[i] = q4(w0[i]);
        ((uint32_t*)g_wq[1])[i] = q4(w1[i]);
        ((uint32_t*)g_wq[2])[i] = q4(w2[i]);
        ((uint32_t*)g_wq[3])[i] = q4(w3[i]);
    }
}
__global__ void k_quant_b(const float* __restrict__ qbv, const float* __restrict__ kb,
                          const float* __restrict__ vb, const float* __restrict__ ob) {
    int i = blockIdx.x * blockDim.x + threadIdx.x;
    if (i < D_) {
        float v;
        v = rintf(qbv[i]*32.f); g_b32[0][i] = (int)fminf(fmaxf(v,-128.f),127.f);
        v = rintf(kb[i]*32.f);  g_b32[1][i] = (int)fminf(fmaxf(v,-128.f),127.f);
        v = rintf(vb[i]*32.f);  g_b32[2][i] = (int)fminf(fmaxf(v,-128.f),127.f);
        v = rintf(ob[i]*32.f);  g_b32[3][i] = (int)fminf(fmaxf(v,-128.f),127.f);
    }
}

// ---------------- IMMA projection GEMM (CTA 128x128, K=1024) ----------------
// C[r][o] = sum_k A[r][k]*W[o][k]; MODE 0->g_q8, 1->g_k8, 2->g_v8t, 3->float out
#define GSTR 48   // padded row stride: conflict-free ldmatrix
template<int MODE>
__global__ void __launch_bounds__(256) k_gemm_mma(float* __restrict__ outf) {
    __shared__ __align__(16) char sA[2][128*GSTR];
    __shared__ __align__(16) char sB[2][128*GSTR];
    const int t = threadIdx.x, lane = t & 31, wid = t >> 5;
    const int wm = wid >> 1, wn = wid & 1;              // 4x2 warp grid
    const int r0 = blockIdx.y << 7, o0 = blockIdx.x << 7;
    const int8_t* Asrc = (MODE == 3) ? g_cq : g_xq;
    const int8_t* Wsrc = g_wq[MODE];
    const int lrow = t >> 1, lhalf = t & 1;

    const uint32_t bA[2] = { smem_u32(sA[0]), smem_u32(sA[1]) };
    const uint32_t bB[2] = { smem_u32(sB[0]), smem_u32(sB[1]) };

    const int mA   = lane >> 3;
    const int arow = (lane & 7) + ((mA & 1) << 3), acol = (mA >> 1) << 4;  // A-style
    const int brow = (lane & 7) + ((mA >> 1) << 3), bcol = (mA & 1) << 4;  // B-style

    int acc[2][8][4];
#pragma unroll
    for (int i = 0; i < 2; i++)
#pragma unroll
        for (int j = 0; j < 8; j++)
#pragma unroll
            for (int e = 0; e < 4; e++) acc[i][j][e] = 0;

    auto prefetch = [&](int kc) {
        cpa16(bA[kc & 1] + lrow*GSTR + lhalf*16,
              Asrc + (size_t)(r0 + lrow)*D_ + kc*32 + lhalf*16);
        cpa16(bB[kc & 1] + lrow*GSTR + lhalf*16,
              Wsrc + (size_t)(o0 + lrow)*D_ + kc*32 + lhalf*16);
    };
    prefetch(0); CPC();

    for (int kc = 0; kc < 32; kc++) {
        if (kc + 1 < 32) { prefetch(kc + 1); CPC(); CPW(1); }
        else             { CPW(0); }
        __syncthreads();
        const uint32_t bufA = bA[kc & 1], bufB = bB[kc & 1];
        uint32_t qa[2][4];
        ldsm4(qa[0], bufA + (wm*32      + arow)*GSTR + acol);
        ldsm4(qa[1], bufA + (wm*32 + 16 + arow)*GSTR + acol);
        uint32_t bfr[4][4];
#pragma unroll
        for (int jp = 0; jp < 4; jp++)
            ldsm4(bfr[jp], bufB + (wn*64 + jp*16 + brow)*GSTR + bcol);
#pragma unroll
        for (int mf = 0; mf < 2; mf++)
#pragma unroll
            for (int jp = 0; jp < 4; jp++) {
                mma16832(acc[mf][jp*2],   qa[mf], bfr[jp][0], bfr[jp][1]);
                mma16832(acc[mf][jp*2+1], qa[mf], bfr[jp][2], bfr[jp][3]);
            }
        __syncthreads();
    }

    // epilogue
    const int tr = lane >> 2, tc2 = (lane & 3) * 2;
#pragma unroll
    for (int mf = 0; mf < 2; mf++)
#pragma unroll
        for (int jf = 0; jf < 8; jf++)
#pragma unroll
            for (int half = 0; half < 2; half++) {
                const int rr = r0 + wm*32 + mf*16 + tr + half*8;
                const int oo = o0 + wn*64 + jf*8 + tc2;
                const int a0 = acc[mf][jf][half*2 + 0];
                const int a1 = acc[mf][jf][half*2 + 1];
                if (MODE == 3) {
                    float2 ov;
                    ov.x = (float)a0*(1.f/1024.f) + (float)g_b32[3][oo]  *(1.f/32.f);
                    ov.y = (float)a1*(1.f/1024.f) + (float)g_b32[3][oo+1]*(1.f/32.f);
                    *(float2*)(outf + (size_t)rr*D_ + oo) = ov;
                } else {
                    const int s0 = a0 + 32*g_b32[MODE][oo];
                    const int s1 = a1 + 32*g_b32[MODE][oo+1];
                    float v0 = (MODE==0) ? rintf((float)s0*(1.f/256.f)) : rintf((float)s0*(1.f/32.f));
                    float v1 = (MODE==0) ? rintf((float)s1*(1.f/256.f)) : rintf((float)s1*(1.f/32.f));
                    v0 = fminf(fmaxf(v0, -128.f), 127.f);
                    v1 = fminf(fmaxf(v1, -128.f), 127.f);
                    const int b  = rr >> 11, n = rr & (N_-1);
                    const int h  = oo >> 6,  hd = oo & (HD_-1);
                    const int bh = b*H_ + h;
                    if (MODE == 0) {
                        *(uint16_t*)(g_q8 + (size_t)(bh*N_ + n)*HD_ + hd) =
                            (uint16_t)(((int)v0 & 255) | (((int)v1 & 255) << 8));
                    } else if (MODE == 1) {
                        *(uint16_t*)(g_k8 + (size_t)(bh*N_ + n)*HD_ + hd) =
                            (uint16_t)(((int)v0 & 255) | (((int)v1 & 255) << 8));
                    } else {
                        g_v8t[(size_t)(bh*HD_ + hd  )*N_ + n] = (int8_t)(int)v0;
                        g_v8t[(size_t)(bh*HD_ + hd+1)*N_ + n] = (int8_t)(int)v1;
                    }
                }
            }
}

// ---------------- fused IMMA flash attention ----------------
// Block = (bh, 128 q-rows), 8 warps x 16 rows. Key-block = 64. 2-pass.
__global__ void __launch_bounds__(256) k_attn_mma(const float* __restrict__ mask) {
    __shared__ __align__(16) char sQ[128*80];
    __shared__ __align__(16) char sK[2][64*80];
    __shared__ __align__(16) char sV[2][64*80];
    __shared__ __align__(16) char sP[8][16*80];

    const int bh = blockIdx.y, rb = blockIdx.x;
    const int t = threadIdx.x, lane = t & 31, w = t >> 5;
    const int bidx = bh >> 4, head = bh & 15;
    const int8_t* Kg = g_k8  + (size_t)bh*N_*HD_;
    const int8_t* Vg = g_v8t + (size_t)bh*HD_*N_;

    const uint32_t uQ    = smem_u32(sQ);
    const uint32_t uK[2] = { smem_u32(sK[0]), smem_u32(sK[1]) };
    const uint32_t uV[2] = { smem_u32(sV[0]), smem_u32(sV[1]) };
    const uint32_t uP    = smem_u32(sP[w]);

    const int mA   = lane >> 3;
    const int arow = (lane & 7) + ((mA & 1) << 3), acol = (mA >> 1) << 4;
    const int brow = (lane & 7) + ((mA >> 1) << 3), bcol = (mA & 1) << 4;
    const int tr = lane >> 2, tc2 = (lane & 3) * 2;

    // Q tile: 128 rows x 64B -> stride 80
    {
        const int8_t* Qg = g_q8 + (size_t)(bh*N_ + rb*128)*HD_;
#pragma unroll
        for (int i = 0; i < 2; i++) {
            int u = t + i*256, row = u >> 2, c = u & 3;
            cpa16(uQ + row*80 + c*16, Qg + row*HD_ + c*16);
        }
    }
    auto copyK = [&](int kb) {
        int row = t >> 2, c = t & 3;
        cpa16(uK[kb & 1] + row*80 + c*16, Kg + (size_t)(kb*64 + row)*HD_ + c*16);
    };
    auto copyV = [&](int kb) {
        int row = t >> 2, c = t & 3;
        cpa16(uV[kb & 1] + row*80 + c*16, Vg + (size_t)row*N_ + kb*64 + c*16);
    };

    const int r0g = rb*128 + w*16 + tr;
    const float* mrow0 = mask + ((size_t)bidx*N_ + r0g)*N_;
    const float* mrow1 = mrow0 + (size_t)8*N_;

    float m0 = FMIN_, m1 = FMIN_, Z0 = 0.f, Z1 = 0.f;

    // ============ pass 1: online max + Z ============
    copyK(0); CPC();
    for (int kb = 0; kb < 32; kb++) {
        if (kb + 1 < 32) { copyK(kb + 1); CPC(); CPW(1); }
        else             { CPW(0); }
        __syncthreads();
        uint32_t qa[2][4];
        ldsm4(qa[0], uQ + (w*16 + arow)*80 +  0 + acol);
        ldsm4(qa[1], uQ + (w*16 + arow)*80 + 32 + acol);
        int sacc[8][4];
#pragma unroll
        for (int j = 0; j < 8; j++)
#pragma unroll
            for (int e = 0; e < 4; e++) sacc[j][e] = 0;
        const uint32_t kbuf = uK[kb & 1];
#pragma unroll
        for (int s = 0; s < 2; s++) {
            uint32_t bfr[4][4];
#pragma unroll
            for (int jp = 0; jp < 4; jp++)
                ldsm4(bfr[jp], kbuf + (jp*16 + brow)*80 + s*32 + bcol);
#pragma unroll
            for (int jp = 0; jp < 4; jp++) {
                mma16832(sacc[jp*2],   qa[s], bfr[jp][0], bfr[jp][1]);
                mma16832(sacc[jp*2+1], qa[s], bfr[jp][2], bfr[jp][3]);
            }
        }
        float bm0 = FMIN_, bm1 = FMIN_;
#pragma unroll
        for (int jf = 0; jf < 8; jf++) {
            float2 mv0 = *(const float2*)(mrow0 + kb*64 + jf*8 + tc2);
            float2 mv1 = *(const float2*)(mrow1 + kb*64 + jf*8 + tc2);
            float s0 = fmaxf((float)sacc[jf][0]*(1.f/1024.f) + mv0.x, FMIN_);
            float s1 = fmaxf((float)sacc[jf][1]*(1.f/1024.f) + mv0.y, FMIN_);
            float s2 = fmaxf((float)sacc[jf][2]*(1.f/1024.f) + mv1.x, FMIN_);
            float s3 = fmaxf((float)sacc[jf][3]*(1.f/1024.f) + mv1.y, FMIN_);
            sacc[jf][0] = __float_as_int(s0); sacc[jf][1] = __float_as_int(s1);
            sacc[jf][2] = __float_as_int(s2); sacc[jf][3] = __float_as_int(s3);
            bm0 = fmaxf(bm0, fmaxf(s0, s1));
            bm1 = fmaxf(bm1, fmaxf(s2, s3));
        }
        bm0 = fmaxf(bm0, __shfl_xor_sync(0xffffffffu, bm0, 1));
        bm0 = fmaxf(bm0, __shfl_xor_sync(0xffffffffu, bm0, 2));
        bm1 = fmaxf(bm1, __shfl_xor_sync(0xffffffffu, bm1, 1));
        bm1 = fmaxf(bm1, __shfl_xor_sync(0xffffffffu, bm1, 2));
        const float nm0 = fmaxf(m0, bm0), nm1 = fmaxf(m1, bm1);
        float l0 = 0.f, l1 = 0.f;
#pragma unroll
        for (int jf = 0; jf < 8; jf++) {
            l0 += __expf(__int_as_float(sacc[jf][0]) - nm0)
                + __expf(__int_as_float(sacc[jf][1]) - nm0);
            l1 += __expf(__int_as_float(sacc[jf][2]) - nm1)
                + __expf(__int_as_float(sacc[jf][3]) - nm1);
        }
        l0 += __shfl_xor_sync(0xffffffffu, l0, 1);
        l0 += __shfl_xor_sync(0xffffffffu, l0, 2);
        l1 += __shfl_xor_sync(0xffffffffu, l1, 1);
        l1 += __shfl_xor_sync(0xffffffffu, l1, 2);
        Z0 = Z0 * __expf(m0 - nm0) + l0;  m0 = nm0;
        Z1 = Z1 * __expf(m1 - nm1) + l1;  m1 = nm1;
        __syncthreads();
    }
    const float c0 = 32.f / Z0, c1 = 32.f / Z1;

    // ============ pass 2: recompute S -> quantize P -> P@V ============
    int cacc[8][4];
#pragma unroll
    for (int j = 0; j < 8; j++)
#pragma unroll
        for (int e = 0; e < 4; e++) cacc[j][e] = 0;

    copyK(0); copyV(0); CPC();
    for (int kb = 0; kb < 32; kb++) {
        if (kb + 1 < 32) { copyK(kb + 1); copyV(kb + 1); CPC(); CPW(1); }
        else             { CPW(0); }
        __syncthreads();
        uint32_t qa[2][4];
        ldsm4(qa[0], uQ + (w*16 + arow)*80 +  0 + acol);
        ldsm4(qa[1], uQ + (w*16 + arow)*80 + 32 + acol);
        int sacc[8][4];
#pragma unroll
        for (int j = 0; j < 8; j++)
#pragma unroll
            for (int e = 0; e < 4; e++) sacc[j][e] = 0;
        const uint32_t kbuf = uK[kb & 1], vbuf = uV[kb & 1];
#pragma unroll
        for (int s = 0; s < 2; s++) {
            uint32_t bfr[4][4];
#pragma unroll
            for (int jp = 0; jp < 4; jp++)
                ldsm4(bfr[jp], kbuf + (jp*16 + brow)*80 + s*32 + bcol);
#pragma unroll
            for (int jp = 0; jp < 4; jp++) {
                mma16832(sacc[jp*2],   qa[s], bfr[jp][0], bfr[jp][1]);
                mma16832(sacc[jp*2+1], qa[s], bfr[jp][2], bfr[jp][3]);
            }
        }
        // quantize probs, pack into A-fragment words, store to per-warp P tile
#pragma unroll
        for (int jf = 0; jf < 8; jf++) {
            float2 mv0 = *(const float2*)(mrow0 + kb*64 + jf*8 + tc2);
            float2 mv1 = *(const float2*)(mrow1 + kb*64 + jf*8 + tc2);
            float s0 = fmaxf((float)sacc[jf][0]*(1.f/1024.f) + mv0.x, FMIN_);
            float s1 = fmaxf((float)sacc[jf][1]*(1.f/1024.f) + mv0.y, FMIN_);
            float s2 = fmaxf((float)sacc[jf][2]*(1.f/1024.f) + mv1.x, FMIN_);
            float s3 = fmaxf((float)sacc[jf][3]*(1.f/1024.f) + mv1.y, FMIN_);
            int p0 = (int)rintf(__expf(s0 - m0) * c0);
            int p1 = (int)rintf(__expf(s1 - m0) * c0);
            int p2 = (int)rintf(__expf(s2 - m1) * c1);
            int p3 = (int)rintf(__expf(s3 - m1) * c1);
            uint32_t w0 = (uint32_t)p0 | ((uint32_t)p1 << 8);
            uint32_t w1 = (uint32_t)p2 | ((uint32_t)p3 << 8);
            uint32_t x0 = __shfl_xor_sync(0xffffffffu, w0, 1);
            uint32_t x1 = __shfl_xor_sync(0xffffffffu, w1, 1);
            if (!(lane & 1)) {
                const int g = (lane & 3) >> 1;
                *(uint32_t*)(sP[w] + (tr    )*80 + jf*8 + g*4) = w0 | (x0 << 16);
                *(uint32_t*)(sP[w] + (tr + 8)*80 + jf*8 + g*4) = w1 | (x1 << 16);
            }
        }
        __syncwarp();
        // P @ V
#pragma unroll
        for (int s = 0; s < 2; s++) {
            uint32_t pa[4];
            ldsm4(pa, uP + arow*80 + s*32 + acol);
            uint32_t vfr[4][4];
#pragma unroll
            for (int jp = 0; jp < 4; jp++)
                ldsm4(vfr[jp], vbuf + (jp*16 + brow)*80 + s*32 + bcol);
#pragma unroll
            for (int jp = 0; jp < 4; jp++) {
                mma16832(cacc[jp*2],   pa, vfr[jp][0], vfr[jp][1]);
                mma16832(cacc[jp*2+1], pa, vfr[jp][2], vfr[jp][3]);
            }
        }
        __syncthreads();
    }

    // ---- ctx epilogue: quantize(ctx) -> g_cq ----
#pragma unroll
    for (int jf = 0; jf < 8; jf++)
#pragma unroll
        for (int half = 0; half < 2; half++) {
            const int rr = r0g + half*8;
            const int hd = jf*8 + tc2;
            float v0 = rintf((float)cacc[jf][half*2+0] * (1.f/32.f));
            float v1 = rintf((float)cacc[jf][half*2+1] * (1.f/32.f));
            v0 = fminf(fmaxf(v0, -128.f), 127.f);
            v1 = fminf(fmaxf(v1, -128.f), 127.f);
            *(uint16_t*)(g_cq + (size_t)(bidx*N_ + rr)*D_ + head*HD_ + hd) =
                (uint16_t)(((int)v0 & 255) | (((int)v1 & 255) << 8));
        }
}

// ---------------- launcher ----------------
extern "C" void kernel_launch(void* const* d_in, const int* in_sizes, int n_in,
                              void* d_out, int out_size) {
    const float* hidden = (const float*)d_in[0];
    const float* amask  = (const float*)d_in[1];
    const float* q_w = (const float*)d_in[2]; const float* q_b = (const float*)d_in[3];
    const float* k_w = (const float*)d_in[4]; const float* k_b = (const float*)d_in[5];
    const float* v_w = (const float*)d_in[6]; const float* v_b = (const float*)d_in[7];
    const float* o_w = (const float*)d_in[8]; const float* o_b = (const float*)d_in[9];
    float* out = (float*)d_out;

    // 1) quantize inputs
    k_quant_x <<<(R_*D_/4 + 255)/256, 256>>>((const float4*)hidden);
    k_quant_w4<<<(D_*D_/4 + 255)/256, 256>>>((const float4*)q_w, (const float4*)k_w,
                                             (const float4*)v_w, (const float4*)o_w);
    k_quant_b <<<(D_ + 255)/256, 256>>>(q_b, k_b, v_b, o_b);

    // 2) projections (IMMA + fused quantize epilogues)
    dim3 gdim(D_/128, R_/128);   // (8, 32)
    k_gemm_mma<0><<<gdim, 256>>>(nullptr);
    k_gemm_mma<1><<<gdim, 256>>>(nullptr);
    k_gemm_mma<2><<<gdim, 256>>>(nullptr);

    // 3) fused IMMA flash attention
    k_attn_mma<<<dim3(N_/128, BH_), 256>>>(amask);

    // 4) output projection -> fp32
    k_gemm_mma<3><<<gdim, 256>>>(out);
}

// round 7
// speedup vs baseline: 3.8146x; 1.0232x over previous
#include <cuda_runtime.h>
#include <stdint.h>

// Problem constants
#define B_   2
#define N_   2048
#define D_   1024
#define H_   16
#define HD_  64
#define BH_  (B_*H_)   // 32
#define R_   (B_*N_)   // 4096

#define FMIN_ (-3.402823466e38f)

// ---------------- device scratch (no allocations allowed) ----------------
__device__ __align__(16) int8_t g_xq[R_*D_];
__device__ __align__(16) int8_t g_wq[4][D_*D_];
__device__ int    g_b32[4][D_];
__device__ __align__(16) int8_t g_q8[BH_*N_*HD_];
__device__ __align__(16) int8_t g_k8[BH_*N_*HD_];
__device__ __align__(16) int8_t g_v8t[BH_*HD_*N_];
__device__ __align__(16) int8_t g_cq[R_*D_];
__device__ __align__(16) float  g_S[(size_t)BH_*N_*N_];   // masked scores (pass1 -> pass2)

// ---------------- base-ISA PTX helpers ----------------
__device__ __forceinline__ uint32_t smem_u32(const void* p) {
    uint32_t a;
    asm("{ .reg .u64 t; cvta.to.shared.u64 t, %1; cvt.u32.u64 %0, t; }" : "=r"(a) : "l"(p));
    return a;
}
__device__ __forceinline__ void cpa16(uint32_t dst, const void* src) {
    uint64_t g = __cvta_generic_to_global(src);
    asm volatile("cp.async.cg.shared.global [%0], [%1], 16;" :: "r"(dst), "l"(g) : "memory");
}
#define CPC()  asm volatile("cp.async.commit_group;" ::: "memory")
#define CPW(n) asm volatile("cp.async.wait_group %0;" :: "n"(n) : "memory")

__device__ __forceinline__ void ldsm4(uint32_t a[4], uint32_t addr) {
    asm volatile("ldmatrix.sync.aligned.m8n8.x4.shared.b16 {%0,%1,%2,%3}, [%4];"
        : "=r"(a[0]), "=r"(a[1]), "=r"(a[2]), "=r"(a[3]) : "r"(addr));
}
__device__ __forceinline__ void mma16832(int c[4], const uint32_t a[4],
                                         uint32_t b0, uint32_t b1) {
    asm volatile(
        "mma.sync.aligned.m16n8k32.row.col.s32.s8.s8.s32 "
        "{%0,%1,%2,%3}, {%4,%5,%6,%7}, {%8,%9}, {%0,%1,%2,%3};"
        : "+r"(c[0]), "+r"(c[1]), "+r"(c[2]), "+r"(c[3])
        : "r"(a[0]), "r"(a[1]), "r"(a[2]), "r"(a[3]), "r"(b0), "r"(b1));
}

// ---------------- quantize kernels ----------------
__device__ __forceinline__ uint32_t qb(float x) {
    float v = rintf(x * 32.f);
    v = fminf(fmaxf(v, -128.f), 127.f);
    return (uint32_t)(int)v & 255u;
}
__device__ __forceinline__ uint32_t q4(float4 v) {
    return qb(v.x) | (qb(v.y) << 8) | (qb(v.z) << 16) | (qb(v.w) << 24);
}
__global__ void k_quant_x(const float4* __restrict__ x) {
    int i = blockIdx.x * blockDim.x + threadIdx.x;
    if (i < R_*D_/4) ((uint32_t*)g_xq)[i] = q4(x[i]);
}
__global__ void k_quant_w4(const float4* __restrict__ w0, const float4* __restrict__ w1,
                           const float4* __restrict__ w2, const float4* __restrict__ w3) {
    int i = blockIdx.x * blockDim.x + threadIdx.x;
    if (i < D_*D_/4) {
        ((uint32_t*)g_wq[0])[i] = q4(w0[i]);
        ((uint32_t*)g_wq[1])[i] = q4(w1[i]);
        ((uint32_t*)g_wq[2])[i] = q4(w2[i]);
        ((uint32_t*)g_wq[3])[i] = q4(w3[i]);
    }
}
__global__ void k_quant_b(const float* __restrict__ qbv, const float* __restrict__ kb,
                          const float* __restrict__ vb, const float* __restrict__ ob) {
    int i = blockIdx.x * blockDim.x + threadIdx.x;
    if (i < D_) {
        float v;
        v = rintf(qbv[i]*32.f); g_b32[0][i] = (int)fminf(fmaxf(v,-128.f),127.f);
        v = rintf(kb[i]*32.f);  g_b32[1][i] = (int)fminf(fmaxf(v,-128.f),127.f);
        v = rintf(vb[i]*32.f);  g_b32[2][i] = (int)fminf(fmaxf(v,-128.f),127.f);
        v = rintf(ob[i]*32.f);  g_b32[3][i] = (int)fminf(fmaxf(v,-128.f),127.f);
    }
}

// ---------------- merged QKV IMMA GEMM (CTA 128x128, K=1024) ----------------
// grid.x = 24: which = x>>3 selects Q/K/V weight + epilogue, (x&7) the N tile.
#define GSTR 48
__global__ void __launch_bounds__(256) k_gemm_qkv() {
    __shared__ __align__(16) char sA[2][128*GSTR];
    __shared__ __align__(16) char sB[2][128*GSTR];
    const int t = threadIdx.x, lane = t & 31, wid = t >> 5;
    const int wm = wid >> 1, wn = wid & 1;
    const int which = blockIdx.x >> 3;
    const int r0 = blockIdx.y << 7, o0 = (blockIdx.x & 7) << 7;
    const int8_t* Asrc = g_xq;
    const int8_t* Wsrc = g_wq[which];
    const int lrow = t >> 1, lhalf = t & 1;

    const uint32_t bA[2] = { smem_u32(sA[0]), smem_u32(sA[1]) };
    const uint32_t bB[2] = { smem_u32(sB[0]), smem_u32(sB[1]) };

    const int mA   = lane >> 3;
    const int arow = (lane & 7) + ((mA & 1) << 3), acol = (mA >> 1) << 4;
    const int brow = (lane & 7) + ((mA >> 1) << 3), bcol = (mA & 1) << 4;

    int acc[2][8][4];
#pragma unroll
    for (int i = 0; i < 2; i++)
#pragma unroll
        for (int j = 0; j < 8; j++)
#pragma unroll
            for (int e = 0; e < 4; e++) acc[i][j][e] = 0;

    auto prefetch = [&](int kc) {
        cpa16(bA[kc & 1] + lrow*GSTR + lhalf*16,
              Asrc + (size_t)(r0 + lrow)*D_ + kc*32 + lhalf*16);
        cpa16(bB[kc & 1] + lrow*GSTR + lhalf*16,
              Wsrc + (size_t)(o0 + lrow)*D_ + kc*32 + lhalf*16);
    };
    prefetch(0); CPC();

    for (int kc = 0; kc < 32; kc++) {
        if (kc + 1 < 32) { prefetch(kc + 1); CPC(); CPW(1); }
        else             { CPW(0); }
        __syncthreads();
        const uint32_t bufA = bA[kc & 1], bufB = bB[kc & 1];
        uint32_t qa[2][4];
        ldsm4(qa[0], bufA + (wm*32      + arow)*GSTR + acol);
        ldsm4(qa[1], bufA + (wm*32 + 16 + arow)*GSTR + acol);
        uint32_t bfr[4][4];
#pragma unroll
        for (int jp = 0; jp < 4; jp++)
            ldsm4(bfr[jp], bufB + (wn*64 + jp*16 + brow)*GSTR + bcol);
#pragma unroll
        for (int mf = 0; mf < 2; mf++)
#pragma unroll
            for (int jp = 0; jp < 4; jp++) {
                mma16832(acc[mf][jp*2],   qa[mf], bfr[jp][0], bfr[jp][1]);
                mma16832(acc[mf][jp*2+1], qa[mf], bfr[jp][2], bfr[jp][3]);
            }
        __syncthreads();
    }

    const float inv = (which == 0) ? (1.f/256.f) : (1.f/32.f);
    const int tr = lane >> 2, tc2 = (lane & 3) * 2;
#pragma unroll
    for (int mf = 0; mf < 2; mf++)
#pragma unroll
        for (int jf = 0; jf < 8; jf++)
#pragma unroll
            for (int half = 0; half < 2; half++) {
                const int rr = r0 + wm*32 + mf*16 + tr + half*8;
                const int oo = o0 + wn*64 + jf*8 + tc2;
                const int s0 = acc[mf][jf][half*2+0] + 32*g_b32[which][oo];
                const int s1 = acc[mf][jf][half*2+1] + 32*g_b32[which][oo+1];
                float v0 = rintf((float)s0 * inv);
                float v1 = rintf((float)s1 * inv);
                v0 = fminf(fmaxf(v0, -128.f), 127.f);
                v1 = fminf(fmaxf(v1, -128.f), 127.f);
                const int b  = rr >> 11, n = rr & (N_-1);
                const int h  = oo >> 6,  hd = oo & (HD_-1);
                const int bh = b*H_ + h;
                if (which == 0) {
                    *(uint16_t*)(g_q8 + (size_t)(bh*N_ + n)*HD_ + hd) =
                        (uint16_t)(((int)v0 & 255) | (((int)v1 & 255) << 8));
                } else if (which == 1) {
                    *(uint16_t*)(g_k8 + (size_t)(bh*N_ + n)*HD_ + hd) =
                        (uint16_t)(((int)v0 & 255) | (((int)v1 & 255) << 8));
                } else {
                    g_v8t[(size_t)(bh*HD_ + hd  )*N_ + n] = (int8_t)(int)v0;
                    g_v8t[(size_t)(bh*HD_ + hd+1)*N_ + n] = (int8_t)(int)v1;
                }
            }
}

// ---------------- O projection (CTA 128x128, K=1024), fp32 out ----------------
__global__ void __launch_bounds__(256) k_gemm_o(float* __restrict__ outf) {
    __shared__ __align__(16) char sA[2][128*GSTR];
    __shared__ __align__(16) char sB[2][128*GSTR];
    const int t = threadIdx.x, lane = t & 31, wid = t >> 5;
    const int wm = wid >> 1, wn = wid & 1;
    const int r0 = blockIdx.y << 7, o0 = blockIdx.x << 7;
    const int lrow = t >> 1, lhalf = t & 1;

    const uint32_t bA[2] = { smem_u32(sA[0]), smem_u32(sA[1]) };
    const uint32_t bB[2] = { smem_u32(sB[0]), smem_u32(sB[1]) };

    const int mA   = lane >> 3;
    const int arow = (lane & 7) + ((mA & 1) << 3), acol = (mA >> 1) << 4;
    const int brow = (lane & 7) + ((mA >> 1) << 3), bcol = (mA & 1) << 4;

    int acc[2][8][4];
#pragma unroll
    for (int i = 0; i < 2; i++)
#pragma unroll
        for (int j = 0; j < 8; j++)
#pragma unroll
            for (int e = 0; e < 4; e++) acc[i][j][e] = 0;

    auto prefetch = [&](int kc) {
        cpa16(bA[kc & 1] + lrow*GSTR + lhalf*16,
              g_cq + (size_t)(r0 + lrow)*D_ + kc*32 + lhalf*16);
        cpa16(bB[kc & 1] + lrow*GSTR + lhalf*16,
              g_wq[3] + (size_t)(o0 + lrow)*D_ + kc*32 + lhalf*16);
    };
    prefetch(0); CPC();

    for (int kc = 0; kc < 32; kc++) {
        if (kc + 1 < 32) { prefetch(kc + 1); CPC(); CPW(1); }
        else             { CPW(0); }
        __syncthreads();
        const uint32_t bufA = bA[kc & 1], bufB = bB[kc & 1];
        uint32_t qa[2][4];
        ldsm4(qa[0], bufA + (wm*32      + arow)*GSTR + acol);
        ldsm4(qa[1], bufA + (wm*32 + 16 + arow)*GSTR + acol);
        uint32_t bfr[4][4];
#pragma unroll
        for (int jp = 0; jp < 4; jp++)
            ldsm4(bfr[jp], bufB + (wn*64 + jp*16 + brow)*GSTR + bcol);
#pragma unroll
        for (int mf = 0; mf < 2; mf++)
#pragma unroll
            for (int jp = 0; jp < 4; jp++) {
                mma16832(acc[mf][jp*2],   qa[mf], bfr[jp][0], bfr[jp][1]);
                mma16832(acc[mf][jp*2+1], qa[mf], bfr[jp][2], bfr[jp][3]);
            }
        __syncthreads();
    }

    const int tr = lane >> 2, tc2 = (lane & 3) * 2;
#pragma unroll
    for (int mf = 0; mf < 2; mf++)
#pragma unroll
        for (int jf = 0; jf < 8; jf++)
#pragma unroll
            for (int half = 0; half < 2; half++) {
                const int rr = r0 + wm*32 + mf*16 + tr + half*8;
                const int oo = o0 + wn*64 + jf*8 + tc2;
                float2 ov;
                ov.x = (float)acc[mf][jf][half*2+0]*(1.f/1024.f) + (float)g_b32[3][oo]  *(1.f/32.f);
                ov.y = (float)acc[mf][jf][half*2+1]*(1.f/1024.f) + (float)g_b32[3][oo+1]*(1.f/32.f);
                *(float2*)(outf + (size_t)rr*D_ + oo) = ov;
            }
}

// ---------------- fused IMMA flash attention (S staged through g_S) ----------------
// Block = (bh, 128 q-rows), 8 warps x 16 rows. Key-block = 64.
// Pass 1: QK -> masked score -> store g_S, online max/Z.
// Pass 2: load g_S -> exp/quantize P -> P@V (no QK recompute).
__global__ void __launch_bounds__(256) k_attn_mma(const float* __restrict__ mask) {
    __shared__ __align__(16) char sQ[128*80];
    __shared__ __align__(16) char sK[2][64*80];
    __shared__ __align__(16) char sV[2][64*80];
    __shared__ __align__(16) char sP[8][16*80];

    const int bh = blockIdx.y, rb = blockIdx.x;
    const int t = threadIdx.x, lane = t & 31, w = t >> 5;
    const int bidx = bh >> 4, head = bh & 15;
    const int8_t* Kg = g_k8  + (size_t)bh*N_*HD_;
    const int8_t* Vg = g_v8t + (size_t)bh*HD_*N_;

    const uint32_t uQ    = smem_u32(sQ);
    const uint32_t uK[2] = { smem_u32(sK[0]), smem_u32(sK[1]) };
    const uint32_t uV[2] = { smem_u32(sV[0]), smem_u32(sV[1]) };
    const uint32_t uP    = smem_u32(sP[w]);

    const int mA   = lane >> 3;
    const int arow = (lane & 7) + ((mA & 1) << 3), acol = (mA >> 1) << 4;
    const int brow = (lane & 7) + ((mA >> 1) << 3), bcol = (mA & 1) << 4;
    const int tr = lane >> 2, tc2 = (lane & 3) * 2;

    // Q tile: 128 rows x 64B -> stride 80
    {
        const int8_t* Qg = g_q8 + (size_t)(bh*N_ + rb*128)*HD_;
#pragma unroll
        for (int i = 0; i < 2; i++) {
            int u = t + i*256, row = u >> 2, c = u & 3;
            cpa16(uQ + row*80 + c*16, Qg + row*HD_ + c*16);
        }
    }
    auto copyK = [&](int kb) {
        int row = t >> 2, c = t & 3;
        cpa16(uK[kb & 1] + row*80 + c*16, Kg + (size_t)(kb*64 + row)*HD_ + c*16);
    };
    auto copyV = [&](int kb) {
        int row = t >> 2, c = t & 3;
        cpa16(uV[kb & 1] + row*80 + c*16, Vg + (size_t)row*N_ + kb*64 + c*16);
    };

    const int r0g = rb*128 + w*16 + tr;
    const float* mrow0 = mask + ((size_t)bidx*N_ + r0g)*N_;
    const float* mrow1 = mrow0 + (size_t)8*N_;
    float* gS0 = g_S + ((size_t)bh*N_ + r0g)*N_;
    float* gS1 = gS0 + (size_t)8*N_;

    float m0 = FMIN_, m1 = FMIN_, Z0 = 0.f, Z1 = 0.f;

    // ============ pass 1: QK -> store S, online max + Z ============
    copyK(0); CPC();
    for (int kb = 0; kb < 32; kb++) {
        if (kb + 1 < 32) { copyK(kb + 1); CPC(); CPW(1); }
        else             { CPW(0); }
        __syncthreads();
        uint32_t qa[2][4];
        ldsm4(qa[0], uQ + (w*16 + arow)*80 +  0 + acol);
        ldsm4(qa[1], uQ + (w*16 + arow)*80 + 32 + acol);
        int sacc[8][4];
#pragma unroll
        for (int j = 0; j < 8; j++)
#pragma unroll
            for (int e = 0; e < 4; e++) sacc[j][e] = 0;
        const uint32_t kbuf = uK[kb & 1];
#pragma unroll
        for (int s = 0; s < 2; s++) {
            uint32_t bfr[4][4];
#pragma unroll
            for (int jp = 0; jp < 4; jp++)
                ldsm4(bfr[jp], kbuf + (jp*16 + brow)*80 + s*32 + bcol);
#pragma unroll
            for (int jp = 0; jp < 4; jp++) {
                mma16832(sacc[jp*2],   qa[s], bfr[jp][0], bfr[jp][1]);
                mma16832(sacc[jp*2+1], qa[s], bfr[jp][2], bfr[jp][3]);
            }
        }
        float bm0 = FMIN_, bm1 = FMIN_;
#pragma unroll
        for (int jf = 0; jf < 8; jf++) {
            float2 mv0 = *(const float2*)(mrow0 + kb*64 + jf*8 + tc2);
            float2 mv1 = *(const float2*)(mrow1 + kb*64 + jf*8 + tc2);
            float s0 = fmaxf((float)sacc[jf][0]*(1.f/1024.f) + mv0.x, FMIN_);
            float s1 = fmaxf((float)sacc[jf][1]*(1.f/1024.f) + mv0.y, FMIN_);
            float s2 = fmaxf((float)sacc[jf][2]*(1.f/1024.f) + mv1.x, FMIN_);
            float s3 = fmaxf((float)sacc[jf][3]*(1.f/1024.f) + mv1.y, FMIN_);
            *(float2*)(gS0 + kb*64 + jf*8 + tc2) = make_float2(s0, s1);
            *(float2*)(gS1 + kb*64 + jf*8 + tc2) = make_float2(s2, s3);
            sacc[jf][0] = __float_as_int(s0); sacc[jf][1] = __float_as_int(s1);
            sacc[jf][2] = __float_as_int(s2); sacc[jf][3] = __float_as_int(s3);
            bm0 = fmaxf(bm0, fmaxf(s0, s1));
            bm1 = fmaxf(bm1, fmaxf(s2, s3));
        }
        bm0 = fmaxf(bm0, __shfl_xor_sync(0xffffffffu, bm0, 1));
        bm0 = fmaxf(bm0, __shfl_xor_sync(0xffffffffu, bm0, 2));
        bm1 = fmaxf(bm1, __shfl_xor_sync(0xffffffffu, bm1, 1));
        bm1 = fmaxf(bm1, __shfl_xor_sync(0xffffffffu, bm1, 2));
        const float nm0 = fmaxf(m0, bm0), nm1 = fmaxf(m1, bm1);
        float l0 = 0.f, l1 = 0.f;
#pragma unroll
        for (int jf = 0; jf < 8; jf++) {
            l0 += __expf(__int_as_float(sacc[jf][0]) - nm0)
                + __expf(__int_as_float(sacc[jf][1]) - nm0);
            l1 += __expf(__int_as_float(sacc[jf][2]) - nm1)
                + __expf(__int_as_float(sacc[jf][3]) - nm1);
        }
        l0 += __shfl_xor_sync(0xffffffffu, l0, 1);
        l0 += __shfl_xor_sync(0xffffffffu, l0, 2);
        l1 += __shfl_xor_sync(0xffffffffu, l1, 1);
        l1 += __shfl_xor_sync(0xffffffffu, l1, 2);
        Z0 = Z0 * __expf(m0 - nm0) + l0;  m0 = nm0;
        Z1 = Z1 * __expf(m1 - nm1) + l1;  m1 = nm1;
        __syncthreads();
    }
    const float c0 = 32.f / Z0, c1 = 32.f / Z1;

    // ============ pass 2: load S -> quantize P -> P@V ============
    int cacc[8][4];
#pragma unroll
    for (int j = 0; j < 8; j++)
#pragma unroll
        for (int e = 0; e < 4; e++) cacc[j][e] = 0;

    copyV(0); CPC();
    for (int kb = 0; kb < 32; kb++) {
        if (kb + 1 < 32) { copyV(kb + 1); CPC(); CPW(1); }
        else             { CPW(0); }
        __syncthreads();
        const uint32_t vbuf = uV[kb & 1];
        // quantize probs from staged S, pack into A-fragment words, store to sP
#pragma unroll
        for (int jf = 0; jf < 8; jf++) {
            float2 sv0 = *(const float2*)(gS0 + kb*64 + jf*8 + tc2);
            float2 sv1 = *(const float2*)(gS1 + kb*64 + jf*8 + tc2);
            int p0 = (int)rintf(__expf(sv0.x - m0) * c0);
            int p1 = (int)rintf(__expf(sv0.y - m0) * c0);
            int p2 = (int)rintf(__expf(sv1.x - m1) * c1);
            int p3 = (int)rintf(__expf(sv1.y - m1) * c1);
            uint32_t w0 = (uint32_t)p0 | ((uint32_t)p1 << 8);
            uint32_t w1 = (uint32_t)p2 | ((uint32_t)p3 << 8);
            uint32_t x0 = __shfl_xor_sync(0xffffffffu, w0, 1);
            uint32_t x1 = __shfl_xor_sync(0xffffffffu, w1, 1);
            if (!(lane & 1)) {
                const int g = (lane & 3) >> 1;
                *(uint32_t*)(sP[w] + (tr    )*80 + jf*8 + g*4) = w0 | (x0 << 16);
                *(uint32_t*)(sP[w] + (tr + 8)*80 + jf*8 + g*4) = w1 | (x1 << 16);
            }
        }
        __syncwarp();
        // P @ V
#pragma unroll
        for (int s = 0; s < 2; s++) {
            uint32_t pa[4];
            ldsm4(pa, uP + arow*80 + s*32 + acol);
            uint32_t vfr[4][4];
#pragma unroll
            for (int jp = 0; jp < 4; jp++)
                ldsm4(vfr[jp], vbuf + (jp*16 + brow)*80 + s*32 + bcol);
#pragma unroll
            for (int jp = 0; jp < 4; jp++) {
                mma16832(cacc[jp*2],   pa, vfr[jp][0], vfr[jp][1]);
                mma16832(cacc[jp*2+1], pa, vfr[jp][2], vfr[jp][3]);
            }
        }
        __syncthreads();
    }

    // ---- ctx epilogue: quantize(ctx) -> g_cq ----
#pragma unroll
    for (int jf = 0; jf < 8; jf++)
#pragma unroll
        for (int half = 0; half < 2; half++) {
            const int rr = r0g + half*8;
            const int hd = jf*8 + tc2;
            float v0 = rintf((float)cacc[jf][half*2+0] * (1.f/32.f));
            float v1 = rintf((float)cacc[jf][half*2+1] * (1.f/32.f));
            v0 = fminf(fmaxf(v0, -128.f), 127.f);
            v1 = fminf(fmaxf(v1, -128.f), 127.f);
            *(uint16_t*)(g_cq + (size_t)(bidx*N_ + rr)*D_ + head*HD_ + hd) =
                (uint16_t)(((int)v0 & 255) | (((int)v1 & 255) << 8));
        }
}

// ---------------- launcher ----------------
extern "C" void kernel_launch(void* const* d_in, const int* in_sizes, int n_in,
                              void* d_out, int out_size) {
    const float* hidden = (const float*)d_in[0];
    const float* amask  = (const float*)d_in[1];
    const float* q_w = (const float*)d_in[2]; const float* q_b = (const float*)d_in[3];
    const float* k_w = (const float*)d_in[4]; const float* k_b = (const float*)d_in[5];
    const float* v_w = (const float*)d_in[6]; const float* v_b = (const float*)d_in[7];
    const float* o_w = (const float*)d_in[8]; const float* o_b = (const float*)d_in[9];
    float* out = (float*)d_out;

    // 1) quantize inputs
    k_quant_x <<<(R_*D_/4 + 255)/256, 256>>>((const float4*)hidden);
    k_quant_w4<<<(D_*D_/4 + 255)/256, 256>>>((const float4*)q_w, (const float4*)k_w,
                                             (const float4*)v_w, (const float4*)o_w);
    k_quant_b <<<(D_ + 255)/256, 256>>>(q_b, k_b, v_b, o_b);

    // 2) merged QKV projection (one launch, 768 CTAs)
    k_gemm_qkv<<<dim3(24, R_/128), 256>>>();

    // 3) fused IMMA flash attention (S staged via g_S)
    k_attn_mma<<<dim3(N_/128, BH_), 256>>>(amask);

    // 4) output projection -> fp32
    k_gemm_o<<<dim3(D_/128, R_/128), 256>>>(out);
}

// round 8
// speedup vs baseline: 4.1399x; 1.0853x over previous
#include <cuda_runtime.h>
#include <stdint.h>

// Problem constants
#define B_   2
#define N_   2048
#define D_   1024
#define H_   16
#define HD_  64
#define BH_  (B_*H_)   // 32
#define R_   (B_*N_)   // 4096

#define FMIN_ (-3.402823466e38f)

// ---------------- device scratch (no allocations allowed) ----------------
__device__ __align__(16) int8_t g_xq[R_*D_];
__device__ __align__(16) int8_t g_wq[4][D_*D_];
__device__ int    g_b32[4][D_];
__device__ __align__(16) int8_t g_q8[BH_*N_*HD_];
__device__ __align__(16) int8_t g_k8[BH_*N_*HD_];
__device__ __align__(16) int8_t g_v8t[BH_*HD_*N_];
__device__ __align__(16) int8_t g_cq[R_*D_];
__device__ __align__(16) float  g_S[(size_t)BH_*N_*N_];   // masked scores (pass1 -> pass2)

// ---------------- base-ISA PTX helpers ----------------
__device__ __forceinline__ uint32_t smem_u32(const void* p) {
    uint32_t a;
    asm("{ .reg .u64 t; cvta.to.shared.u64 t, %1; cvt.u32.u64 %0, t; }" : "=r"(a) : "l"(p));
    return a;
}
__device__ __forceinline__ void cpa16(uint32_t dst, const void* src) {
    uint64_t g = __cvta_generic_to_global(src);
    asm volatile("cp.async.cg.shared.global [%0], [%1], 16;" :: "r"(dst), "l"(g) : "memory");
}
#define CPC()  asm volatile("cp.async.commit_group;" ::: "memory")
#define CPW(n) asm volatile("cp.async.wait_group %0;" :: "n"(n) : "memory")

__device__ __forceinline__ void ldsm4(uint32_t a[4], uint32_t addr) {
    asm volatile("ldmatrix.sync.aligned.m8n8.x4.shared.b16 {%0,%1,%2,%3}, [%4];"
        : "=r"(a[0]), "=r"(a[1]), "=r"(a[2]), "=r"(a[3]) : "r"(addr));
}
__device__ __forceinline__ void mma16832(int c[4], const uint32_t a[4],
                                         uint32_t b0, uint32_t b1) {
    asm volatile(
        "mma.sync.aligned.m16n8k32.row.col.s32.s8.s8.s32 "
        "{%0,%1,%2,%3}, {%4,%5,%6,%7}, {%8,%9}, {%0,%1,%2,%3};"
        : "+r"(c[0]), "+r"(c[1]), "+r"(c[2]), "+r"(c[3])
        : "r"(a[0]), "r"(a[1]), "r"(a[2]), "r"(a[3]), "r"(b0), "r"(b1));
}

// ---------------- quantize kernels ----------------
__device__ __forceinline__ uint32_t qb(float x) {
    float v = rintf(x * 32.f);
    v = fminf(fmaxf(v, -128.f), 127.f);
    return (uint32_t)(int)v & 255u;
}
__device__ __forceinline__ uint32_t q4(float4 v) {
    return qb(v.x) | (qb(v.y) << 8) | (qb(v.z) << 16) | (qb(v.w) << 24);
}
__global__ void k_quant_x(const float4* __restrict__ x) {
    int i = blockIdx.x * blockDim.x + threadIdx.x;
    if (i < R_*D_/4) ((uint32_t*)g_xq)[i] = q4(x[i]);
}
__global__ void k_quant_w4(const float4* __restrict__ w0, const float4* __restrict__ w1,
                           const float4* __restrict__ w2, const float4* __restrict__ w3) {
    int i = blockIdx.x * blockDim.x + threadIdx.x;
    if (i < D_*D_/4) {
        ((uint32_t*)g_wq[0])[i] = q4(w0[i]);
        ((uint32_t*)g_wq[1])[i] = q4(w1[i]);
        ((uint32_t*)g_wq[2])[i] = q4(w2[i]);
        ((uint32_t*)g_wq[3])[i] = q4(w3[i]);
    }
}
__global__ void k_quant_b(const float* __restrict__ qbv, const float* __restrict__ kb,
                          const float* __restrict__ vb, const float* __restrict__ ob) {
    int i = blockIdx.x * blockDim.x + threadIdx.x;
    if (i < D_) {
        float v;
        v = rintf(qbv[i]*32.f); g_b32[0][i] = (int)fminf(fmaxf(v,-128.f),127.f);
        v = rintf(kb[i]*32.f);  g_b32[1][i] = (int)fminf(fmaxf(v,-128.f),127.f);
        v = rintf(vb[i]*32.f);  g_b32[2][i] = (int)fminf(fmaxf(v,-128.f),127.f);
        v = rintf(ob[i]*32.f);  g_b32[3][i] = (int)fminf(fmaxf(v,-128.f),127.f);
    }
}

// ---------------- IMMA GEMM core: 3-stage ring, 1 sync/iter ----------------
#define GSTR 48
// MODE: 0=Q 1=K 2=V (merged launch via which), 3=O
template<int IS_O>
__device__ __forceinline__ void gemm_body(const int8_t* Asrc, const int8_t* Wsrc,
                                          int which, int r0, int o0,
                                          float* __restrict__ outf) {
    __shared__ __align__(16) char sA[3][128*GSTR];
    __shared__ __align__(16) char sB[3][128*GSTR];
    const int t = threadIdx.x, lane = t & 31, wid = t >> 5;
    const int wm = wid >> 1, wn = wid & 1;
    const int lrow = t >> 1, lhalf = t & 1;

    uint32_t bA[3], bB[3];
#pragma unroll
    for (int s = 0; s < 3; s++) { bA[s] = smem_u32(sA[s]); bB[s] = smem_u32(sB[s]); }

    const int mA   = lane >> 3;
    const int arow = (lane & 7) + ((mA & 1) << 3), acol = (mA >> 1) << 4;
    const int brow = (lane & 7) + ((mA >> 1) << 3), bcol = (mA & 1) << 4;

    int acc[2][8][4];
#pragma unroll
    for (int i = 0; i < 2; i++)
#pragma unroll
        for (int j = 0; j < 8; j++)
#pragma unroll
            for (int e = 0; e < 4; e++) acc[i][j][e] = 0;

    auto prefetch = [&](int kc) {
        const int s = kc % 3;
        cpa16(bA[s] + lrow*GSTR + lhalf*16,
              Asrc + (size_t)(r0 + lrow)*D_ + kc*32 + lhalf*16);
        cpa16(bB[s] + lrow*GSTR + lhalf*16,
              Wsrc + (size_t)(o0 + lrow)*D_ + kc*32 + lhalf*16);
    };
    prefetch(0); CPC();
    prefetch(1); CPC();
    CPW(1); __syncthreads();

    for (int kc = 0; kc < 32; kc++) {
        if (kc + 2 < 32) { prefetch(kc + 2); CPC(); }
        const int s = kc % 3;
        const uint32_t bufA = bA[s], bufB = bB[s];
        uint32_t qa[2][4];
        ldsm4(qa[0], bufA + (wm*32      + arow)*GSTR + acol);
        ldsm4(qa[1], bufA + (wm*32 + 16 + arow)*GSTR + acol);
        uint32_t bfr[4][4];
#pragma unroll
        for (int jp = 0; jp < 4; jp++)
            ldsm4(bfr[jp], bufB + (wn*64 + jp*16 + brow)*GSTR + bcol);
#pragma unroll
        for (int mf = 0; mf < 2; mf++)
#pragma unroll
            for (int jp = 0; jp < 4; jp++) {
                mma16832(acc[mf][jp*2],   qa[mf], bfr[jp][0], bfr[jp][1]);
                mma16832(acc[mf][jp*2+1], qa[mf], bfr[jp][2], bfr[jp][3]);
            }
        CPW(1); __syncthreads();
    }

    const int tr = lane >> 2, tc2 = (lane & 3) * 2;
    const float inv = (which == 0) ? (1.f/256.f) : (1.f/32.f);
#pragma unroll
    for (int mf = 0; mf < 2; mf++)
#pragma unroll
        for (int jf = 0; jf < 8; jf++)
#pragma unroll
            for (int half = 0; half < 2; half++) {
                const int rr = r0 + wm*32 + mf*16 + tr + half*8;
                const int oo = o0 + wn*64 + jf*8 + tc2;
                if (IS_O) {
                    float2 ov;
                    ov.x = (float)acc[mf][jf][half*2+0]*(1.f/1024.f) + (float)g_b32[3][oo]  *(1.f/32.f);
                    ov.y = (float)acc[mf][jf][half*2+1]*(1.f/1024.f) + (float)g_b32[3][oo+1]*(1.f/32.f);
                    *(float2*)(outf + (size_t)rr*D_ + oo) = ov;
                } else {
                    const int s0 = acc[mf][jf][half*2+0] + 32*g_b32[which][oo];
                    const int s1 = acc[mf][jf][half*2+1] + 32*g_b32[which][oo+1];
                    float v0 = rintf((float)s0 * inv);
                    float v1 = rintf((float)s1 * inv);
                    v0 = fminf(fmaxf(v0, -128.f), 127.f);
                    v1 = fminf(fmaxf(v1, -128.f), 127.f);
                    const int b  = rr >> 11, n = rr & (N_-1);
                    const int h  = oo >> 6,  hd = oo & (HD_-1);
                    const int bh = b*H_ + h;
                    if (which == 0) {
                        *(uint16_t*)(g_q8 + (size_t)(bh*N_ + n)*HD_ + hd) =
                            (uint16_t)(((int)v0 & 255) | (((int)v1 & 255) << 8));
                    } else if (which == 1) {
                        *(uint16_t*)(g_k8 + (size_t)(bh*N_ + n)*HD_ + hd) =
                            (uint16_t)(((int)v0 & 255) | (((int)v1 & 255) << 8));
                    } else {
                        g_v8t[(size_t)(bh*HD_ + hd  )*N_ + n] = (int8_t)(int)v0;
                        g_v8t[(size_t)(bh*HD_ + hd+1)*N_ + n] = (int8_t)(int)v1;
                    }
                }
            }
}

__global__ void __launch_bounds__(256) k_gemm_qkv() {
    const int which = blockIdx.x >> 3;
    gemm_body<0>(g_xq, g_wq[which], which,
                 blockIdx.y << 7, (blockIdx.x & 7) << 7, nullptr);
}
__global__ void __launch_bounds__(256) k_gemm_o(float* __restrict__ outf) {
    gemm_body<1>(g_cq, g_wq[3], 3, blockIdx.y << 7, blockIdx.x << 7, outf);
}

// ---------------- fused IMMA flash attention ----------------
// Block = (bh, 128 q-rows), 8 warps x 16 rows. Key-block = 64, 3-stage ring.
// Pass 1: QK -> masked score -> store g_S, online max/Z.
// Pass 2 (reverse kb for L2 hits on S): load g_S -> exp/quantize P -> P@V.
__global__ void __launch_bounds__(256, 2) k_attn_mma(const float* __restrict__ mask) {
    __shared__ __align__(16) char sQ[128*80];
    __shared__ __align__(16) char sKV[3][64*80];   // K ring (pass1) / V ring (pass2)
    __shared__ __align__(16) char sP[8][16*80];

    const int bh = blockIdx.y, rb = blockIdx.x;
    const int t = threadIdx.x, lane = t & 31, w = t >> 5;
    const int bidx = bh >> 4, head = bh & 15;
    const int8_t* Kg = g_k8  + (size_t)bh*N_*HD_;
    const int8_t* Vg = g_v8t + (size_t)bh*HD_*N_;

    const uint32_t uQ = smem_u32(sQ);
    uint32_t uKV[3];
#pragma unroll
    for (int s = 0; s < 3; s++) uKV[s] = smem_u32(sKV[s]);
    const uint32_t uP = smem_u32(sP[w]);

    const int mA   = lane >> 3;
    const int arow = (lane & 7) + ((mA & 1) << 3), acol = (mA >> 1) << 4;
    const int brow = (lane & 7) + ((mA >> 1) << 3), bcol = (mA & 1) << 4;
    const int tr = lane >> 2, tc2 = (lane & 3) * 2;

    auto copyK = [&](int kb) {
        int row = t >> 2, c = t & 3;
        cpa16(uKV[kb % 3] + row*80 + c*16, Kg + (size_t)(kb*64 + row)*HD_ + c*16);
    };
    auto copyV = [&](int kb) {
        int row = t >> 2, c = t & 3;
        cpa16(uKV[kb % 3] + row*80 + c*16, Vg + (size_t)row*N_ + kb*64 + c*16);
    };

    // Q tile (group 0)
    {
        const int8_t* Qg = g_q8 + (size_t)(bh*N_ + rb*128)*HD_;
#pragma unroll
        for (int i = 0; i < 2; i++) {
            int u = t + i*256, row = u >> 2, c = u & 3;
            cpa16(uQ + row*80 + c*16, Qg + row*HD_ + c*16);
        }
        CPC();
    }
    copyK(0); CPC();
    copyK(1); CPC();
    CPW(1); __syncthreads();           // Q + K0 ready

    // hoisted Q fragments (loop-invariant)
    uint32_t qa[2][4];
    ldsm4(qa[0], uQ + (w*16 + arow)*80 +  0 + acol);
    ldsm4(qa[1], uQ + (w*16 + arow)*80 + 32 + acol);

    const int r0g = rb*128 + w*16 + tr;
    const float* mrow0 = mask + ((size_t)bidx*N_ + r0g)*N_;
    const float* mrow1 = mrow0 + (size_t)8*N_;
    float* gS0 = g_S + ((size_t)bh*N_ + r0g)*N_;
    float* gS1 = gS0 + (size_t)8*N_;

    float m0 = FMIN_, m1 = FMIN_, Z0 = 0.f, Z1 = 0.f;

    // ============ pass 1: QK -> store S, online max + Z ============
    for (int kb = 0; kb < 32; kb++) {
        if (kb + 2 < 32) { copyK(kb + 2); CPC(); }
        int sacc[8][4];
#pragma unroll
        for (int j = 0; j < 8; j++)
#pragma unroll
            for (int e = 0; e < 4; e++) sacc[j][e] = 0;
        const uint32_t kbuf = uKV[kb % 3];
#pragma unroll
        for (int s = 0; s < 2; s++) {
            uint32_t bfr[4][4];
#pragma unroll
            for (int jp = 0; jp < 4; jp++)
                ldsm4(bfr[jp], kbuf + (jp*16 + brow)*80 + s*32 + bcol);
#pragma unroll
            for (int jp = 0; jp < 4; jp++) {
                mma16832(sacc[jp*2],   qa[s], bfr[jp][0], bfr[jp][1]);
                mma16832(sacc[jp*2+1], qa[s], bfr[jp][2], bfr[jp][3]);
            }
        }
        float bm0 = FMIN_, bm1 = FMIN_;
#pragma unroll
        for (int jf = 0; jf < 8; jf++) {
            float2 mv0 = *(const float2*)(mrow0 + kb*64 + jf*8 + tc2);
            float2 mv1 = *(const float2*)(mrow1 + kb*64 + jf*8 + tc2);
            float s0 = fmaxf((float)sacc[jf][0]*(1.f/1024.f) + mv0.x, FMIN_);
            float s1 = fmaxf((float)sacc[jf][1]*(1.f/1024.f) + mv0.y, FMIN_);
            float s2 = fmaxf((float)sacc[jf][2]*(1.f/1024.f) + mv1.x, FMIN_);
            float s3 = fmaxf((float)sacc[jf][3]*(1.f/1024.f) + mv1.y, FMIN_);
            *(float2*)(gS0 + kb*64 + jf*8 + tc2) = make_float2(s0, s1);
            *(float2*)(gS1 + kb*64 + jf*8 + tc2) = make_float2(s2, s3);
            sacc[jf][0] = __float_as_int(s0); sacc[jf][1] = __float_as_int(s1);
            sacc[jf][2] = __float_as_int(s2); sacc[jf][3] = __float_as_int(s3);
            bm0 = fmaxf(bm0, fmaxf(s0, s1));
            bm1 = fmaxf(bm1, fmaxf(s2, s3));
        }
        bm0 = fmaxf(bm0, __shfl_xor_sync(0xffffffffu, bm0, 1));
        bm0 = fmaxf(bm0, __shfl_xor_sync(0xffffffffu, bm0, 2));
        bm1 = fmaxf(bm1, __shfl_xor_sync(0xffffffffu, bm1, 1));
        bm1 = fmaxf(bm1, __shfl_xor_sync(0xffffffffu, bm1, 2));
        const float nm0 = fmaxf(m0, bm0), nm1 = fmaxf(m1, bm1);
        float l0 = 0.f, l1 = 0.f;
#pragma unroll
        for (int jf = 0; jf < 8; jf++) {
            l0 += __expf(__int_as_float(sacc[jf][0]) - nm0)
                + __expf(__int_as_float(sacc[jf][1]) - nm0);
            l1 += __expf(__int_as_float(sacc[jf][2]) - nm1)
                + __expf(__int_as_float(sacc[jf][3]) - nm1);
        }
        l0 += __shfl_xor_sync(0xffffffffu, l0, 1);
        l0 += __shfl_xor_sync(0xffffffffu, l0, 2);
        l1 += __shfl_xor_sync(0xffffffffu, l1, 1);
        l1 += __shfl_xor_sync(0xffffffffu, l1, 2);
        Z0 = Z0 * __expf(m0 - nm0) + l0;  m0 = nm0;
        Z1 = Z1 * __expf(m1 - nm1) + l1;  m1 = nm1;
        CPW(1); __syncthreads();
    }
    const float c0 = 32.f / Z0, c1 = 32.f / Z1;
    CPW(0); __syncthreads();   // drain before KV ring reuse

    // ============ pass 2 (reverse): load S -> quantize P -> P@V ============
    int cacc[8][4];
#pragma unroll
    for (int j = 0; j < 8; j++)
#pragma unroll
        for (int e = 0; e < 4; e++) cacc[j][e] = 0;

    copyV(31); CPC();
    copyV(30); CPC();
    CPW(1); __syncthreads();

    for (int i = 0; i < 32; i++) {
        const int kb = 31 - i;
        if (kb - 2 >= 0) { copyV(kb - 2); CPC(); }
        const uint32_t vbuf = uKV[kb % 3];
        // quantize probs from staged S (two half-batches for LDG ILP)
#pragma unroll
        for (int hf = 0; hf < 2; hf++) {
            float2 sv0[4], sv1[4];
#pragma unroll
            for (int q = 0; q < 4; q++) {
                sv0[q] = *(const float2*)(gS0 + kb*64 + (hf*4+q)*8 + tc2);
                sv1[q] = *(const float2*)(gS1 + kb*64 + (hf*4+q)*8 + tc2);
            }
#pragma unroll
            for (int q = 0; q < 4; q++) {
                const int jf = hf*4 + q;
                int p0 = (int)rintf(__expf(sv0[q].x - m0) * c0);
                int p1 = (int)rintf(__expf(sv0[q].y - m0) * c0);
                int p2 = (int)rintf(__expf(sv1[q].x - m1) * c1);
                int p3 = (int)rintf(__expf(sv1[q].y - m1) * c1);
                uint32_t w0 = (uint32_t)p0 | ((uint32_t)p1 << 8);
                uint32_t w1 = (uint32_t)p2 | ((uint32_t)p3 << 8);
                uint32_t x0 = __shfl_xor_sync(0xffffffffu, w0, 1);
                uint32_t x1 = __shfl_xor_sync(0xffffffffu, w1, 1);
                if (!(lane & 1)) {
                    const int g = (lane & 3) >> 1;
                    *(uint32_t*)(sP[w] + (tr    )*80 + jf*8 + g*4) = w0 | (x0 << 16);
                    *(uint32_t*)(sP[w] + (tr + 8)*80 + jf*8 + g*4) = w1 | (x1 << 16);
                }
            }
        }
        __syncwarp();
        // P @ V
#pragma unroll
        for (int s = 0; s < 2; s++) {
            uint32_t pa[4];
            ldsm4(pa, uP + arow*80 + s*32 + acol);
            uint32_t vfr[4][4];
#pragma unroll
            for (int jp = 0; jp < 4; jp++)
                ldsm4(vfr[jp], vbuf + (jp*16 + brow)*80 + s*32 + bcol);
#pragma unroll
            for (int jp = 0; jp < 4; jp++) {
                mma16832(cacc[jp*2],   pa, vfr[jp][0], vfr[jp][1]);
                mma16832(cacc[jp*2+1], pa, vfr[jp][2], vfr[jp][3]);
            }
        }
        CPW(1); __syncthreads();
    }

    // ---- ctx epilogue: quantize(ctx) -> g_cq ----
#pragma unroll
    for (int jf = 0; jf < 8; jf++)
#pragma unroll
        for (int half = 0; half < 2; half++) {
            const int rr = r0g + half*8;
            const int hd = jf*8 + tc2;
            float v0 = rintf((float)cacc[jf][half*2+0] * (1.f/32.f));
            float v1 = rintf((float)cacc[jf][half*2+1] * (1.f/32.f));
            v0 = fminf(fmaxf(v0, -128.f), 127.f);
            v1 = fminf(fmaxf(v1, -128.f), 127.f);
            *(uint16_t*)(g_cq + (size_t)(bidx*N_ + rr)*D_ + head*HD_ + hd) =
                (uint16_t)(((int)v0 & 255) | (((int)v1 & 255) << 8));
        }
}

// ---------------- launcher ----------------
extern "C" void kernel_launch(void* const* d_in, const int* in_sizes, int n_in,
                              void* d_out, int out_size) {
    const float* hidden = (const float*)d_in[0];
    const float* amask  = (const float*)d_in[1];
    const float* q_w = (const float*)d_in[2]; const float* q_b = (const float*)d_in[3];
    const float* k_w = (const float*)d_in[4]; const float* k_b = (const float*)d_in[5];
    const float* v_w = (const float*)d_in[6]; const float* v_b = (const float*)d_in[7];
    const float* o_w = (const float*)d_in[8]; const float* o_b = (const float*)d_in[9];
    float* out = (float*)d_out;

    // 1) quantize inputs
    k_quant_x <<<(R_*D_/4 + 255)/256, 256>>>((const float4*)hidden);
    k_quant_w4<<<(D_*D_/4 + 255)/256, 256>>>((const float4*)q_w, (const float4*)k_w,
                                             (const float4*)v_w, (const float4*)o_w);
    k_quant_b <<<(D_ + 255)/256, 256>>>(q_b, k_b, v_b, o_b);

    // 2) merged QKV projection (one launch, 768 CTAs)
    k_gemm_qkv<<<dim3(24, R_/128), 256>>>();

    // 3) fused IMMA flash attention (S staged via g_S, reverse pass 2)
    k_attn_mma<<<dim3(N_/128, BH_), 256>>>(amask);

    // 4) output projection -> fp32
    k_gemm_o<<<dim3(D_/128, R_/128), 256>>>(out);
}